// round 5
// baseline (speedup 1.0000x reference)
#include <cuda_runtime.h>
#include <cuda_bf16.h>
#include <cstdint>

// N=65536, K=256, D=512, ALPHA=1, fp32 in/out.
#define D_DIM  512
#define K_CL   256
#define BM     128
#define KC     64
#define NCHUNK 8
#define CB_CHUNK_BYTES (K_CL * KC * 2)   // 32768

// smem byte offsets
#define OFF_A0   0        // 128 x 128B = 16384
#define OFF_A1   16384
#define OFF_B0   32768    // 256 x 128B = 32768
#define OFF_B1   65536
#define OFF_C2S  98304    // 256 f32
#define OFF_X2S  99328    // 128 f32
#define OFF_PART 99840    // 128*4 f32
#define OFF_INV  101888   // 128 f32
#define SMEM_TOTAL 102400
#define STAGE_PITCH 264   // 64 rows * 264 * 4B = 67584 <= 98304 (reuses GEMM buffers)

__device__ __align__(16) unsigned char g_cb[NCHUNK * CB_CHUNK_BYTES]; // 256KB bf16 swizzled
__device__ float g_c2[K_CL];

__device__ __forceinline__ uint32_t sw128(uint32_t off) { return off ^ ((off >> 3) & 0x70); }

__device__ __forceinline__ uint32_t smem_u32(const void* p) {
    uint32_t a;
    asm("{ .reg .u64 t; cvta.to.shared.u64 t, %1; cvt.u32.u64 %0, t; }" : "=r"(a) : "l"(p));
    return a;
}
__device__ __forceinline__ float frcp(float x) {
    float r; asm("rcp.approx.f32 %0, %1;" : "=f"(r) : "f"(x)); return r;
}
__device__ __forceinline__ void ldsm_x4(uint32_t (&r)[4], uint32_t addr) {
    asm volatile("ldmatrix.sync.aligned.m8n8.x4.shared.b16 {%0,%1,%2,%3}, [%4];"
                 : "=r"(r[0]), "=r"(r[1]), "=r"(r[2]), "=r"(r[3]) : "r"(addr));
}
__device__ __forceinline__ void mma16816(float (&d)[4], const uint32_t (&a)[4],
                                         uint32_t b0, uint32_t b1) {
    asm volatile("mma.sync.aligned.m16n8k16.row.col.f32.bf16.bf16.f32 "
                 "{%0,%1,%2,%3}, {%4,%5,%6,%7}, {%8,%9}, {%0,%1,%2,%3};"
                 : "+f"(d[0]), "+f"(d[1]), "+f"(d[2]), "+f"(d[3])
                 : "r"(a[0]), "r"(a[1]), "r"(a[2]), "r"(a[3]), "r"(b0), "r"(b1));
}
#define CP_ASYNC16(dst, src) \
    asm volatile("cp.async.cg.shared.global [%0], [%1], 16;" :: "r"(dst), "l"(src) : "memory")
#define CP_COMMIT() asm volatile("cp.async.commit_group;" ::: "memory")
#define CP_WAIT0()  asm volatile("cp.async.wait_group 0;" ::: "memory")

// ---- prepass: clusters fp32 -> bf16 chunk-blocked + SW128-swizzled, plus c2 norms ----
__global__ void prep_c_kernel(const float* __restrict__ C) {
    int w = (blockIdx.x * blockDim.x + threadIdx.x) >> 5;  // one warp per cluster row
    int lane = threadIdx.x & 31;
    if (w >= K_CL) return;
    const float4* src = reinterpret_cast<const float4*>(C + (size_t)w * D_DIM);
    float s = 0.f;
#pragma unroll
    for (int i = 0; i < 4; i++) {
        int f4 = lane + 32 * i;
        float4 v = src[f4];
        s += v.x * v.x + v.y * v.y + v.z * v.z + v.w * v.w;
        __nv_bfloat162 h0 = __float22bfloat162_rn(make_float2(v.x, v.y));
        __nv_bfloat162 h1 = __float22bfloat162_rn(make_float2(v.z, v.w));
        int col = f4 * 4;
        int chunk = col >> 6, kin = col & 63;
        uint32_t off = (uint32_t)chunk * CB_CHUNK_BYTES + sw128((uint32_t)w * 128 + kin * 2);
        *reinterpret_cast<uint2*>(g_cb + off) =
            make_uint2(*(uint32_t*)&h0, *(uint32_t*)&h1);
    }
#pragma unroll
    for (int o = 16; o; o >>= 1) s += __shfl_xor_sync(0xffffffffu, s, o);
    if (lane == 0) g_c2[w] = s;
}

// ---- main fused kernel: BM=128, 8 warps, warp tile 64x64 ----
extern __shared__ char smem[];

__global__ __launch_bounds__(256, 1)
void cluster_q_kernel(const float* __restrict__ X, float* __restrict__ out) {
    const int tid = threadIdx.x;
    const int lane = tid & 31;
    const int w = tid >> 5, wm = w >> 2, wn = w & 3;  // wm in {0,1}, wn in 0..3
    const int rowBase = blockIdx.x * BM;
    const uint32_t sb = smem_u32(smem);

    ((float*)(smem + OFF_C2S))[tid] = g_c2[tid];

    // A-load mapping: 2 threads per row, 8 float4 each per chunk
    const int ar = tid >> 1;          // 0..127
    const int af = tid & 1;           // half of the 64-col chunk
    const float4* Xg =
        reinterpret_cast<const float4*>(X + (size_t)(rowBase + ar) * D_DIM) + af * 8;

    // precomputed swizzled fragment offsets (kb folds in via XOR: kb is bits 5-6,
    // swizzle mask depends only on bits 7-9 -> no interaction)
    uint32_t qA[4], qB[4];
    {
        const uint32_t t16a = (lane >> 4) * 16;
        const uint32_t t16b = ((lane >> 3) & 1) * 16;
#pragma unroll
        for (int mi = 0; mi < 4; mi++) {
            uint32_t row = wm * 64 + mi * 16 + ((lane >> 3) & 1) * 8 + (lane & 7);
            uint32_t base = row * 128;
            qA[mi] = base + (t16a ^ ((base >> 3) & 0x70));
        }
#pragma unroll
        for (int nt = 0; nt < 4; nt++) {
            uint32_t row = wn * 64 + nt * 16 + ((lane >> 4) & 1) * 8 + (lane & 7);
            uint32_t base = row * 128;
            qB[nt] = base + (t16b ^ ((base >> 3) & 0x70));
        }
    }

    float acc[4][8][4];
#pragma unroll
    for (int a = 0; a < 4; a++)
#pragma unroll
        for (int b = 0; b < 8; b++)
#pragma unroll
            for (int c = 0; c < 4; c++) acc[a][b][c] = 0.f;
    float rsx = 0.f;
    float4 xv[8];

    auto issueB = [&](int chunk, uint32_t bufoff) {
        const unsigned char* src = g_cb + (size_t)chunk * CB_CHUNK_BYTES;
#pragma unroll
        for (int i = 0; i < 8; i++) {
            uint32_t u = tid + 256 * i;
            CP_ASYNC16(sb + bufoff + u * 16, src + u * 16);
        }
    };
    auto loadX = [&](int chunk) {
#pragma unroll
        for (int i = 0; i < 8; i++) xv[i] = Xg[chunk * 16 + i];
    };
    auto storeA = [&](uint32_t bufoff) {
#pragma unroll
        for (int i = 0; i < 8; i++) {
            float4 v = xv[i];
            rsx = fmaf(v.x, v.x, fmaf(v.y, v.y, fmaf(v.z, v.z, fmaf(v.w, v.w, rsx))));
            __nv_bfloat162 h0 = __float22bfloat162_rn(make_float2(v.x, v.y));
            __nv_bfloat162 h1 = __float22bfloat162_rn(make_float2(v.z, v.w));
            uint32_t off = sw128((uint32_t)ar * 128 + (af * 8 + i) * 8);
            *reinterpret_cast<uint2*>(smem + bufoff + off) =
                make_uint2(*(uint32_t*)&h0, *(uint32_t*)&h1);
        }
    };
    auto mmaChunk = [&](uint32_t aoff, uint32_t boff) {
#pragma unroll
        for (int ks = 0; ks < 4; ks++) {
            const uint32_t kb = ks * 32;
            uint32_t afr[4][4];
#pragma unroll
            for (int mi = 0; mi < 4; mi++) ldsm_x4(afr[mi], sb + aoff + (qA[mi] ^ kb));
#pragma unroll
            for (int nt = 0; nt < 4; nt++) {
                uint32_t bfr[4];
                ldsm_x4(bfr, sb + boff + (qB[nt] ^ kb));
#pragma unroll
                for (int mi = 0; mi < 4; mi++) {
                    mma16816(acc[mi][2 * nt], afr[mi], bfr[0], bfr[1]);
                    mma16816(acc[mi][2 * nt + 1], afr[mi], bfr[2], bfr[3]);
                }
            }
        }
    };

    // pipeline
    issueB(0, OFF_B0);
    CP_COMMIT();
    loadX(0);
    CP_WAIT0();
    storeA(OFF_A0);
    __syncthreads();
    for (int chunk = 0; chunk < NCHUNK; chunk++) {
        const uint32_t ao = (chunk & 1) ? OFF_A1 : OFF_A0;
        const uint32_t bo = (chunk & 1) ? OFF_B1 : OFF_B0;
        const uint32_t ano = (chunk & 1) ? OFF_A0 : OFF_A1;
        const uint32_t bno = (chunk & 1) ? OFF_B0 : OFF_B1;
        if (chunk + 1 < NCHUNK) {
            issueB(chunk + 1, bno);
            CP_COMMIT();
            loadX(chunk + 1);
        }
        mmaChunk(ao, bo);
        if (chunk + 1 < NCHUNK) {
            CP_WAIT0();
            storeA(ano);
        }
        __syncthreads();
    }

    // x2 norms: 2 lanes share row ar
    rsx += __shfl_xor_sync(0xffffffffu, rsx, 1);
    float* x2s = (float*)(smem + OFF_X2S);
    if (af == 0) x2s[ar] = rsx;
    __syncthreads();

    // ---- epilogue phase 1: q (overwrites acc) + row partial sums ----
    float* c2s = (float*)(smem + OFF_C2S);
    float* part = (float*)(smem + OFF_PART);   // [128][4]
    float* invs = (float*)(smem + OFF_INV);

#pragma unroll
    for (int mi = 0; mi < 4; mi++) {
        const int r0 = wm * 64 + mi * 16 + (lane >> 2);
        const float xr0 = x2s[r0];
        const float xr1 = x2s[r0 + 8];
        float p0 = 0.f, p1 = 0.f;
#pragma unroll
        for (int ni = 0; ni < 8; ni++) {
            const int col = wn * 64 + ni * 8 + 2 * (lane & 3);
            const float c20 = c2s[col], c21 = c2s[col + 1];
            float q00 = frcp(1.f + fmaxf(fmaf(-2.f, acc[mi][ni][0], xr0 + c20), 0.f));
            float q01 = frcp(1.f + fmaxf(fmaf(-2.f, acc[mi][ni][1], xr0 + c21), 0.f));
            float q10 = frcp(1.f + fmaxf(fmaf(-2.f, acc[mi][ni][2], xr1 + c20), 0.f));
            float q11 = frcp(1.f + fmaxf(fmaf(-2.f, acc[mi][ni][3], xr1 + c21), 0.f));
            p0 += q00 + q01;
            p1 += q10 + q11;
            acc[mi][ni][0] = q00; acc[mi][ni][1] = q01;
            acc[mi][ni][2] = q10; acc[mi][ni][3] = q11;
        }
        p0 += __shfl_xor_sync(0xffffffffu, p0, 1);
        p0 += __shfl_xor_sync(0xffffffffu, p0, 2);
        p1 += __shfl_xor_sync(0xffffffffu, p1, 1);
        p1 += __shfl_xor_sync(0xffffffffu, p1, 2);
        if ((lane & 3) == 0) {
            part[r0 * 4 + wn] = p0;
            part[(r0 + 8) * 4 + wn] = p1;
        }
    }
    __syncthreads();
    if (tid < 128)
        invs[tid] = frcp(part[tid * 4] + part[tid * 4 + 1] + part[tid * 4 + 2] + part[tid * 4 + 3]);
    __syncthreads();

    // ---- epilogue phase 2: two staged 64-row passes (rows are wm-partitioned) ----
    float* stage = (float*)smem;   // [64][STAGE_PITCH]
#pragma unroll
    for (int p = 0; p < 2; p++) {
        if (wm == p) {
#pragma unroll
            for (int mi = 0; mi < 4; mi++) {
                const int rl = mi * 16 + (lane >> 2);   // local row in pass
#pragma unroll
                for (int ni = 0; ni < 8; ni++) {
                    const int col = wn * 64 + ni * 8 + 2 * (lane & 3);
                    *reinterpret_cast<float2*>(&stage[rl * STAGE_PITCH + col]) =
                        make_float2(acc[mi][ni][0], acc[mi][ni][1]);
                    *reinterpret_cast<float2*>(&stage[(rl + 8) * STAGE_PITCH + col]) =
                        make_float2(acc[mi][ni][2], acc[mi][ni][3]);
                }
            }
        }
        __syncthreads();
        {
            const int rl = tid >> 2;
            const float iv = invs[p * 64 + rl];
            float* orow = out + (size_t)(rowBase + p * 64 + rl) * K_CL;
#pragma unroll
            for (int i = 0; i < 16; i++) {
                const int c4 = (tid & 3) + 4 * i;
                float4 v = *reinterpret_cast<float4*>(&stage[rl * STAGE_PITCH + 4 * c4]);
                v.x *= iv; v.y *= iv; v.z *= iv; v.w *= iv;
                *reinterpret_cast<float4*>(&orow[4 * c4]) = v;
            }
        }
        __syncthreads();
    }
}

extern "C" void kernel_launch(void* const* d_in, const int* in_sizes, int n_in,
                              void* d_out, int out_size) {
    const float* X = (const float*)d_in[0];   // [65536, 512]
    const float* C = (const float*)d_in[1];   // [256, 512]
    float* out = (float*)d_out;               // [65536, 256]
    const int n = in_sizes[0] / D_DIM;

    cudaFuncSetAttribute(cluster_q_kernel, cudaFuncAttributeMaxDynamicSharedMemorySize,
                         SMEM_TOTAL);
    prep_c_kernel<<<32, 256>>>(C);
    cluster_q_kernel<<<n / BM, 256, SMEM_TOTAL>>>(X, out);
}

// round 6
// speedup vs baseline: 1.4868x; 1.4868x over previous
#include <cuda_runtime.h>
#include <cuda_bf16.h>
#include <cstdint>

// N=65536, K=256, D=512, ALPHA=1, fp32 in/out.
#define D_DIM  512
#define K_CL   256
#define BM     64
#define KC     64
#define NCHUNK 8
#define CB_CHUNK_BYTES (K_CL * KC * 2)   // 32768

// smem byte offsets
#define OFF_A0   0        // 64 x 128B  = 8192
#define OFF_A1   8192
#define OFF_B0   16384    // 256 x 128B = 32768
#define OFF_B1   49152
#define OFF_C2S  81920    // 256 f32
#define OFF_X2S  82944    // 64 f32
#define OFF_PART 83200    // 64*4 f32
#define OFF_INV  84224    // 64 f32
#define SMEM_TOTAL 84480

__device__ __align__(16) unsigned char g_cb[NCHUNK * CB_CHUNK_BYTES]; // 256KB bf16 swizzled
__device__ float g_c2[K_CL];

__device__ __forceinline__ uint32_t sw128(uint32_t off) { return off ^ ((off >> 3) & 0x70); }

__device__ __forceinline__ uint32_t smem_u32(const void* p) {
    uint32_t a;
    asm("{ .reg .u64 t; cvta.to.shared.u64 t, %1; cvt.u32.u64 %0, t; }" : "=r"(a) : "l"(p));
    return a;
}
__device__ __forceinline__ float frcp(float x) {
    float r; asm("rcp.approx.f32 %0, %1;" : "=f"(r) : "f"(x)); return r;
}
__device__ __forceinline__ void ldsm_x4(uint32_t (&r)[4], uint32_t addr) {
    asm volatile("ldmatrix.sync.aligned.m8n8.x4.shared.b16 {%0,%1,%2,%3}, [%4];"
                 : "=r"(r[0]), "=r"(r[1]), "=r"(r[2]), "=r"(r[3]) : "r"(addr));
}
__device__ __forceinline__ void mma16816(float (&d)[4], const uint32_t (&a)[4],
                                         uint32_t b0, uint32_t b1) {
    asm volatile("mma.sync.aligned.m16n8k16.row.col.f32.bf16.bf16.f32 "
                 "{%0,%1,%2,%3}, {%4,%5,%6,%7}, {%8,%9}, {%0,%1,%2,%3};"
                 : "+f"(d[0]), "+f"(d[1]), "+f"(d[2]), "+f"(d[3])
                 : "r"(a[0]), "r"(a[1]), "r"(a[2]), "r"(a[3]), "r"(b0), "r"(b1));
}
#define CP_ASYNC16(dst, src) \
    asm volatile("cp.async.cg.shared.global [%0], [%1], 16;" :: "r"(dst), "l"(src) : "memory")
#define CP_COMMIT() asm volatile("cp.async.commit_group;" ::: "memory")
#define CP_WAIT0()  asm volatile("cp.async.wait_group 0;" ::: "memory")

// ---- prepass: clusters fp32 -> bf16 chunk-blocked + SW128-swizzled, plus c2 norms ----
__global__ void prep_c_kernel(const float* __restrict__ C) {
    int w = (blockIdx.x * blockDim.x + threadIdx.x) >> 5;  // one warp per cluster row
    int lane = threadIdx.x & 31;
    if (w >= K_CL) return;
    const float4* src = reinterpret_cast<const float4*>(C + (size_t)w * D_DIM);
    float s = 0.f;
#pragma unroll
    for (int i = 0; i < 4; i++) {
        int f4 = lane + 32 * i;
        float4 v = src[f4];
        s += v.x * v.x + v.y * v.y + v.z * v.z + v.w * v.w;
        __nv_bfloat162 h0 = __float22bfloat162_rn(make_float2(v.x, v.y));
        __nv_bfloat162 h1 = __float22bfloat162_rn(make_float2(v.z, v.w));
        int col = f4 * 4;
        int chunk = col >> 6, kin = col & 63;
        uint32_t off = (uint32_t)chunk * CB_CHUNK_BYTES + sw128((uint32_t)w * 128 + kin * 2);
        *reinterpret_cast<uint2*>(g_cb + off) =
            make_uint2(*(uint32_t*)&h0, *(uint32_t*)&h1);
    }
#pragma unroll
    for (int o = 16; o; o >>= 1) s += __shfl_xor_sync(0xffffffffu, s, o);
    if (lane == 0) g_c2[w] = s;
}

// ---- main fused kernel: BM=64, 8 warps, warp tile 32x64 (proven R3 GEMM) ----
extern __shared__ char smem[];

__global__ __launch_bounds__(256, 2)
void cluster_q_kernel(const float* __restrict__ X, float* __restrict__ out) {
    const int tid = threadIdx.x;
    const int lane = tid & 31;
    const int w = tid >> 5, wm = w >> 2, wn = w & 3;
    const int rowBase = blockIdx.x * BM;
    const uint32_t sb = smem_u32(smem);

    ((float*)(smem + OFF_C2S))[tid] = g_c2[tid];

    // A-load mapping: thread -> row ar, float4 base af; 4 float4/chunk
    const int ar = tid >> 2;
    const int af = tid & 3;
    const float4* Xg = reinterpret_cast<const float4*>(X + (size_t)(rowBase + ar) * D_DIM) + af;

    float acc[2][8][4];
#pragma unroll
    for (int a = 0; a < 2; a++)
#pragma unroll
        for (int b = 0; b < 8; b++)
#pragma unroll
            for (int c = 0; c < 4; c++) acc[a][b][c] = 0.f;
    float rsx = 0.f;
    float4 xv[4];

    auto issueB = [&](int chunk, uint32_t bufoff) {
        const unsigned char* src = g_cb + (size_t)chunk * CB_CHUNK_BYTES;
#pragma unroll
        for (int i = 0; i < 8; i++) {
            uint32_t u = tid + 256 * i;
            CP_ASYNC16(sb + bufoff + u * 16, src + u * 16);
        }
    };
    auto loadX = [&](int chunk) {
#pragma unroll
        for (int i = 0; i < 4; i++) xv[i] = Xg[chunk * 16 + 4 * i];
    };
    auto storeA = [&](uint32_t bufoff) {
#pragma unroll
        for (int i = 0; i < 4; i++) {
            float4 v = xv[i];
            rsx = fmaf(v.x, v.x, fmaf(v.y, v.y, fmaf(v.z, v.z, fmaf(v.w, v.w, rsx))));
            __nv_bfloat162 h0 = __float22bfloat162_rn(make_float2(v.x, v.y));
            __nv_bfloat162 h1 = __float22bfloat162_rn(make_float2(v.z, v.w));
            uint32_t off = sw128((uint32_t)ar * 128 + (af + 4 * i) * 8);
            *reinterpret_cast<uint2*>(smem + bufoff + off) =
                make_uint2(*(uint32_t*)&h0, *(uint32_t*)&h1);
        }
    };
    auto mmaChunk = [&](uint32_t aoff, uint32_t boff) {
#pragma unroll
        for (int ks = 0; ks < 4; ks++) {
            const uint32_t kb = ks * 32;
            uint32_t afr[2][4];
#pragma unroll
            for (int mi = 0; mi < 2; mi++) {
                int row = wm * 32 + mi * 16 + ((lane >> 3) & 1) * 8 + (lane & 7);
                uint32_t kbyte = kb + (lane >> 4) * 16;
                ldsm_x4(afr[mi], sb + aoff + sw128((uint32_t)row * 128 + kbyte));
            }
#pragma unroll
            for (int nt = 0; nt < 4; nt++) {
                uint32_t bfr[4];
                int nrow = wn * 64 + nt * 16 + ((lane >> 4) & 1) * 8 + (lane & 7);
                uint32_t kbyte = kb + ((lane >> 3) & 1) * 16;
                ldsm_x4(bfr, sb + boff + sw128((uint32_t)nrow * 128 + kbyte));
#pragma unroll
                for (int mi = 0; mi < 2; mi++) {
                    mma16816(acc[mi][2 * nt], afr[mi], bfr[0], bfr[1]);
                    mma16816(acc[mi][2 * nt + 1], afr[mi], bfr[2], bfr[3]);
                }
            }
        }
    };

    // pipeline
    issueB(0, OFF_B0);
    CP_COMMIT();
    loadX(0);
    CP_WAIT0();
    storeA(OFF_A0);
    __syncthreads();
    for (int chunk = 0; chunk < NCHUNK; chunk++) {
        const uint32_t ao = (chunk & 1) ? OFF_A1 : OFF_A0;
        const uint32_t bo = (chunk & 1) ? OFF_B1 : OFF_B0;
        const uint32_t ano = (chunk & 1) ? OFF_A0 : OFF_A1;
        const uint32_t bno = (chunk & 1) ? OFF_B0 : OFF_B1;
        if (chunk + 1 < NCHUNK) {
            issueB(chunk + 1, bno);
            CP_COMMIT();
            loadX(chunk + 1);
        }
        mmaChunk(ao, bo);
        if (chunk + 1 < NCHUNK) {
            CP_WAIT0();
            storeA(ano);
        }
        __syncthreads();
    }

    // x2 norms: 4 lanes share row ar
    rsx += __shfl_xor_sync(0xffffffffu, rsx, 1);
    rsx += __shfl_xor_sync(0xffffffffu, rsx, 2);
    float* x2s = (float*)(smem + OFF_X2S);
    if ((tid & 3) == 0) x2s[ar] = rsx;
    __syncthreads();

    // ---- epilogue phase 1: q (overwrites acc) + row partial sums ----
    float* c2s = (float*)(smem + OFF_C2S);
    float* part = (float*)(smem + OFF_PART);   // [64][4]
    float* invs = (float*)(smem + OFF_INV);

#pragma unroll
    for (int mi = 0; mi < 2; mi++) {
        const int r0 = wm * 32 + mi * 16 + (lane >> 2);
        const float xr0 = x2s[r0];
        const float xr1 = x2s[r0 + 8];
        float p0 = 0.f, p1 = 0.f;
#pragma unroll
        for (int ni = 0; ni < 8; ni++) {
            const int col = wn * 64 + ni * 8 + 2 * (lane & 3);
            const float c20 = c2s[col], c21 = c2s[col + 1];
            float q00 = frcp(1.f + fmaxf(fmaf(-2.f, acc[mi][ni][0], xr0 + c20), 0.f));
            float q01 = frcp(1.f + fmaxf(fmaf(-2.f, acc[mi][ni][1], xr0 + c21), 0.f));
            float q10 = frcp(1.f + fmaxf(fmaf(-2.f, acc[mi][ni][2], xr1 + c20), 0.f));
            float q11 = frcp(1.f + fmaxf(fmaf(-2.f, acc[mi][ni][3], xr1 + c21), 0.f));
            p0 += q00 + q01;
            p1 += q10 + q11;
            acc[mi][ni][0] = q00; acc[mi][ni][1] = q01;
            acc[mi][ni][2] = q10; acc[mi][ni][3] = q11;
        }
        p0 += __shfl_xor_sync(0xffffffffu, p0, 1);
        p0 += __shfl_xor_sync(0xffffffffu, p0, 2);
        p1 += __shfl_xor_sync(0xffffffffu, p1, 1);
        p1 += __shfl_xor_sync(0xffffffffu, p1, 2);
        if ((lane & 3) == 0) {
            part[r0 * 4 + wn] = p0;
            part[(r0 + 8) * 4 + wn] = p1;
        }
    }
    __syncthreads();
    if (tid < 64)
        invs[tid] = frcp(part[tid * 4] + part[tid * 4 + 1] + part[tid * 4 + 2] + part[tid * 4 + 3]);
    __syncthreads();

    // ---- epilogue phase 2: direct fragment stores (no smem staging) ----
    // Each quad of lanes writes one aligned 32B segment per (mi,ni,row-half):
    // cols wn*64+ni*8 .. +8 are 32B-aligned -> sector-perfect STG.64.
#pragma unroll
    for (int mi = 0; mi < 2; mi++) {
        const int r0 = wm * 32 + mi * 16 + (lane >> 2);
        const float iv0 = invs[r0];
        const float iv1 = invs[r0 + 8];
        float* orow0 = out + (size_t)(rowBase + r0) * K_CL;
        float* orow1 = out + (size_t)(rowBase + r0 + 8) * K_CL;
#pragma unroll
        for (int ni = 0; ni < 8; ni++) {
            const int col = wn * 64 + ni * 8 + 2 * (lane & 3);
            *reinterpret_cast<float2*>(&orow0[col]) =
                make_float2(acc[mi][ni][0] * iv0, acc[mi][ni][1] * iv0);
            *reinterpret_cast<float2*>(&orow1[col]) =
                make_float2(acc[mi][ni][2] * iv1, acc[mi][ni][3] * iv1);
        }
    }
}

extern "C" void kernel_launch(void* const* d_in, const int* in_sizes, int n_in,
                              void* d_out, int out_size) {
    const float* X = (const float*)d_in[0];   // [65536, 512]
    const float* C = (const float*)d_in[1];   // [256, 512]
    float* out = (float*)d_out;               // [65536, 256]
    const int n = in_sizes[0] / D_DIM;

    cudaFuncSetAttribute(cluster_q_kernel, cudaFuncAttributeMaxDynamicSharedMemorySize,
                         SMEM_TOTAL);
    prep_c_kernel<<<32, 256>>>(C);
    cluster_q_kernel<<<n / BM, 256, SMEM_TOTAL>>>(X, out);
}

// round 8
// speedup vs baseline: 1.5228x; 1.0242x over previous
#include <cuda_runtime.h>
#include <cuda_bf16.h>
#include <cstdint>

// N=65536, K=256, D=512, ALPHA=1, fp32 in/out.
#define D_DIM  512
#define K_CL   256
#define BM     64
#define KC     64
#define NCHUNK 8
#define CB_CHUNK_BYTES (K_CL * KC * 2)   // 32768

// smem byte offsets
#define OFF_A0   0        // 64 x 128B  = 8192
#define OFF_A1   8192
#define OFF_B0   16384    // 256 x 128B = 32768
#define OFF_B1   49152
#define OFF_C2S  81920    // 256 f32
#define OFF_X2S  82944    // 64 f32
#define OFF_PART 83200    // 64*4 f32
#define OFF_INV  84224    // 64 f32
#define SMEM_TOTAL 84480

__device__ __align__(16) unsigned char g_cb[NCHUNK * CB_CHUNK_BYTES]; // 256KB bf16 swizzled
__device__ float g_c2[K_CL];

__device__ __forceinline__ uint32_t sw128(uint32_t off) { return off ^ ((off >> 3) & 0x70); }

__device__ __forceinline__ uint32_t smem_u32(const void* p) {
    uint32_t a;
    asm("{ .reg .u64 t; cvta.to.shared.u64 t, %1; cvt.u32.u64 %0, t; }" : "=r"(a) : "l"(p));
    return a;
}
__device__ __forceinline__ float frcp(float x) {
    float r; asm("rcp.approx.f32 %0, %1;" : "=f"(r) : "f"(x)); return r;
}
__device__ __forceinline__ void ldsm_x4(uint32_t (&r)[4], uint32_t addr) {
    asm volatile("ldmatrix.sync.aligned.m8n8.x4.shared.b16 {%0,%1,%2,%3}, [%4];"
                 : "=r"(r[0]), "=r"(r[1]), "=r"(r[2]), "=r"(r[3]) : "r"(addr));
}
__device__ __forceinline__ void mma16816(float (&d)[4], const uint32_t (&a)[4],
                                         uint32_t b0, uint32_t b1) {
    asm volatile("mma.sync.aligned.m16n8k16.row.col.f32.bf16.bf16.f32 "
                 "{%0,%1,%2,%3}, {%4,%5,%6,%7}, {%8,%9}, {%0,%1,%2,%3};"
                 : "+f"(d[0]), "+f"(d[1]), "+f"(d[2]), "+f"(d[3])
                 : "r"(a[0]), "r"(a[1]), "r"(a[2]), "r"(a[3]), "r"(b0), "r"(b1));
}
#define CP_ASYNC16(dst, src) \
    asm volatile("cp.async.cg.shared.global [%0], [%1], 16;" :: "r"(dst), "l"(src) : "memory")
#define CP_COMMIT() asm volatile("cp.async.commit_group;" ::: "memory")
#define CP_WAIT0()  asm volatile("cp.async.wait_group 0;" ::: "memory")

// ---- prepass: clusters fp32 -> bf16 chunk-blocked + SW128-swizzled, plus c2 norms ----
__global__ void prep_c_kernel(const float* __restrict__ C) {
    int w = (blockIdx.x * blockDim.x + threadIdx.x) >> 5;  // one warp per cluster row
    int lane = threadIdx.x & 31;
    if (w >= K_CL) return;
    const float4* src = reinterpret_cast<const float4*>(C + (size_t)w * D_DIM);
    float s = 0.f;
#pragma unroll
    for (int i = 0; i < 4; i++) {
        int f4 = lane + 32 * i;
        float4 v = src[f4];
        s += v.x * v.x + v.y * v.y + v.z * v.z + v.w * v.w;
        __nv_bfloat162 h0 = __float22bfloat162_rn(make_float2(v.x, v.y));
        __nv_bfloat162 h1 = __float22bfloat162_rn(make_float2(v.z, v.w));
        int col = f4 * 4;
        int chunk = col >> 6, kin = col & 63;
        uint32_t off = (uint32_t)chunk * CB_CHUNK_BYTES + sw128((uint32_t)w * 128 + kin * 2);
        *reinterpret_cast<uint2*>(g_cb + off) =
            make_uint2(*(uint32_t*)&h0, *(uint32_t*)&h1);
    }
#pragma unroll
    for (int o = 16; o; o >>= 1) s += __shfl_xor_sync(0xffffffffu, s, o);
    if (lane == 0) g_c2[w] = s;
}

// ---- main fused kernel: BM=64, 8 warps, warp tile 32x64, hoisted frag addresses ----
extern __shared__ char smem[];

__global__ __launch_bounds__(256, 2)
void cluster_q_kernel(const float* __restrict__ X, float* __restrict__ out) {
    const int tid = threadIdx.x;
    const int lane = tid & 31;
    const int w = tid >> 5, wm = w >> 2, wn = w & 3;
    const int rowBase = blockIdx.x * BM;
    const uint32_t sb = smem_u32(smem);

    ((float*)(smem + OFF_C2S))[tid] = g_c2[tid];

    // A-load mapping: thread -> row ar, float4 base af; 4 float4/chunk
    const int ar = tid >> 2;
    const int af = tid & 3;
    const float4* Xg = reinterpret_cast<const float4*>(X + (size_t)(rowBase + ar) * D_DIM) + af;

    // hoisted swizzled fragment base offsets; per-ks address = q ^ kb
    // (kb = ks*32 occupies bits 5-6: no carry past bit 7, swizzle mask reads bits 7-9
    //  only, and t16+kb == t16^kb since bit sets are disjoint)
    uint32_t qA[2], qB[4];
    {
        const uint32_t t16a = (lane >> 4) * 16;
        const uint32_t t16b = ((lane >> 3) & 1) * 16;
#pragma unroll
        for (int mi = 0; mi < 2; mi++) {
            uint32_t row = wm * 32 + mi * 16 + ((lane >> 3) & 1) * 8 + (lane & 7);
            uint32_t base = row * 128;
            qA[mi] = base + (t16a ^ ((base >> 3) & 0x70));
        }
#pragma unroll
        for (int nt = 0; nt < 4; nt++) {
            uint32_t row = wn * 64 + nt * 16 + ((lane >> 4) & 1) * 8 + (lane & 7);
            uint32_t base = row * 128;
            qB[nt] = base + (t16b ^ ((base >> 3) & 0x70));
        }
    }

    float acc[2][8][4];
#pragma unroll
    for (int a = 0; a < 2; a++)
#pragma unroll
        for (int b = 0; b < 8; b++)
#pragma unroll
            for (int c = 0; c < 4; c++) acc[a][b][c] = 0.f;
    float rsx = 0.f;
    float4 xv[4];

    auto issueB = [&](int chunk, uint32_t bufoff) {
        const unsigned char* src = g_cb + (size_t)chunk * CB_CHUNK_BYTES;
#pragma unroll
        for (int i = 0; i < 8; i++) {
            uint32_t u = tid + 256 * i;
            CP_ASYNC16(sb + bufoff + u * 16, src + u * 16);
        }
    };
    auto loadX = [&](int chunk) {
#pragma unroll
        for (int i = 0; i < 4; i++) xv[i] = Xg[chunk * 16 + 4 * i];
    };
    auto storeA = [&](uint32_t bufoff) {
#pragma unroll
        for (int i = 0; i < 4; i++) {
            float4 v = xv[i];
            rsx = fmaf(v.x, v.x, fmaf(v.y, v.y, fmaf(v.z, v.z, fmaf(v.w, v.w, rsx))));
            __nv_bfloat162 h0 = __float22bfloat162_rn(make_float2(v.x, v.y));
            __nv_bfloat162 h1 = __float22bfloat162_rn(make_float2(v.z, v.w));
            uint32_t off = sw128((uint32_t)ar * 128 + (af + 4 * i) * 8);
            *reinterpret_cast<uint2*>(smem + bufoff + off) =
                make_uint2(*(uint32_t*)&h0, *(uint32_t*)&h1);
        }
    };
    auto mmaChunk = [&](uint32_t aoff, uint32_t boff) {
#pragma unroll
        for (int ks = 0; ks < 4; ks++) {
            const uint32_t kb = ks * 32;
            uint32_t afr[2][4];
#pragma unroll
            for (int mi = 0; mi < 2; mi++) ldsm_x4(afr[mi], sb + aoff + (qA[mi] ^ kb));
#pragma unroll
            for (int nt = 0; nt < 4; nt++) {
                uint32_t bfr[4];
                ldsm_x4(bfr, sb + boff + (qB[nt] ^ kb));
#pragma unroll
                for (int mi = 0; mi < 2; mi++) {
                    mma16816(acc[mi][2 * nt], afr[mi], bfr[0], bfr[1]);
                    mma16816(acc[mi][2 * nt + 1], afr[mi], bfr[2], bfr[3]);
                }
            }
        }
    };

    // pipeline
    issueB(0, OFF_B0);
    CP_COMMIT();
    loadX(0);
    CP_WAIT0();
    storeA(OFF_A0);
    __syncthreads();
    for (int chunk = 0; chunk < NCHUNK; chunk++) {
        const uint32_t ao = (chunk & 1) ? OFF_A1 : OFF_A0;
        const uint32_t bo = (chunk & 1) ? OFF_B1 : OFF_B0;
        const uint32_t ano = (chunk & 1) ? OFF_A0 : OFF_A1;
        const uint32_t bno = (chunk & 1) ? OFF_B0 : OFF_B1;
        if (chunk + 1 < NCHUNK) {
            issueB(chunk + 1, bno);
            CP_COMMIT();
            loadX(chunk + 1);
        }
        mmaChunk(ao, bo);
        if (chunk + 1 < NCHUNK) {
            CP_WAIT0();
            storeA(ano);
        }
        __syncthreads();
    }

    // x2 norms: 4 lanes share row ar
    rsx += __shfl_xor_sync(0xffffffffu, rsx, 1);
    rsx += __shfl_xor_sync(0xffffffffu, rsx, 2);
    float* x2s = (float*)(smem + OFF_X2S);
    if ((tid & 3) == 0) x2s[ar] = rsx;
    __syncthreads();

    // ---- epilogue phase 1: q (overwrites acc) + row partial sums ----
    float* c2s = (float*)(smem + OFF_C2S);
    float* part = (float*)(smem + OFF_PART);   // [64][4]
    float* invs = (float*)(smem + OFF_INV);

#pragma unroll
    for (int mi = 0; mi < 2; mi++) {
        const int r0 = wm * 32 + mi * 16 + (lane >> 2);
        const float xr0 = x2s[r0];
        const float xr1 = x2s[r0 + 8];
        float p0 = 0.f, p1 = 0.f;
#pragma unroll
        for (int ni = 0; ni < 8; ni++) {
            const int col = wn * 64 + ni * 8 + 2 * (lane & 3);
            const float c20 = c2s[col], c21 = c2s[col + 1];
            float q00 = frcp(1.f + fmaxf(fmaf(-2.f, acc[mi][ni][0], xr0 + c20), 0.f));
            float q01 = frcp(1.f + fmaxf(fmaf(-2.f, acc[mi][ni][1], xr0 + c21), 0.f));
            float q10 = frcp(1.f + fmaxf(fmaf(-2.f, acc[mi][ni][2], xr1 + c20), 0.f));
            float q11 = frcp(1.f + fmaxf(fmaf(-2.f, acc[mi][ni][3], xr1 + c21), 0.f));
            p0 += q00 + q01;
            p1 += q10 + q11;
            acc[mi][ni][0] = q00; acc[mi][ni][1] = q01;
            acc[mi][ni][2] = q10; acc[mi][ni][3] = q11;
        }
        p0 += __shfl_xor_sync(0xffffffffu, p0, 1);
        p0 += __shfl_xor_sync(0xffffffffu, p0, 2);
        p1 += __shfl_xor_sync(0xffffffffu, p1, 1);
        p1 += __shfl_xor_sync(0xffffffffu, p1, 2);
        if ((lane & 3) == 0) {
            part[r0 * 4 + wn] = p0;
            part[(r0 + 8) * 4 + wn] = p1;
        }
    }
    __syncthreads();
    if (tid < 64)
        invs[tid] = frcp(part[tid * 4] + part[tid * 4 + 1] + part[tid * 4 + 2] + part[tid * 4 + 3]);
    __syncthreads();

    // ---- epilogue phase 2: direct fragment stores (no smem staging) ----
#pragma unroll
    for (int mi = 0; mi < 2; mi++) {
        const int r0 = wm * 32 + mi * 16 + (lane >> 2);
        const float iv0 = invs[r0];
        const float iv1 = invs[r0 + 8];
        float* orow0 = out + (size_t)(rowBase + r0) * K_CL;
        float* orow1 = out + (size_t)(rowBase + r0 + 8) * K_CL;
#pragma unroll
        for (int ni = 0; ni < 8; ni++) {
            const int col = wn * 64 + ni * 8 + 2 * (lane & 3);
            *reinterpret_cast<float2*>(&orow0[col]) =
                make_float2(acc[mi][ni][0] * iv0, acc[mi][ni][1] * iv0);
            *reinterpret_cast<float2*>(&orow1[col]) =
                make_float2(acc[mi][ni][2] * iv1, acc[mi][ni][3] * iv1);
        }
    }
}

extern "C" void kernel_launch(void* const* d_in, const int* in_sizes, int n_in,
                              void* d_out, int out_size) {
    const float* X = (const float*)d_in[0];   // [65536, 512]
    const float* C = (const float*)d_in[1];   // [256, 512]
    float* out = (float*)d_out;               // [65536, 256]
    const int n = in_sizes[0] / D_DIM;

    cudaFuncSetAttribute(cluster_q_kernel, cudaFuncAttributeMaxDynamicSharedMemorySize,
                         SMEM_TOTAL);
    prep_c_kernel<<<32, 256>>>(C);
    cluster_q_kernel<<<n / BM, 256, SMEM_TOTAL>>>(X, out);
}

// round 9
// speedup vs baseline: 1.6226x; 1.0656x over previous
#include <cuda_runtime.h>
#include <cuda_bf16.h>
#include <cstdint>

// N=65536, K=256, D=512, ALPHA=1, fp32 in/out.
#define D_DIM  512
#define K_CL   256
#define BM     64
#define KC     64
#define NCHUNK 8
#define CB_CHUNK_BYTES (K_CL * KC * 2)   // 32768

// smem byte offsets
#define OFF_A0   0        // 64 x 128B  = 8192
#define OFF_A1   8192
#define OFF_B0   16384    // 256 x 128B = 32768
#define OFF_B1   49152
#define OFF_C2S  81920    // 256 f32
#define OFF_X2S  82944    // 64 f32
#define OFF_PART 83200    // 64*4 f32
#define OFF_INV  84224    // 64 f32
#define SM_MBAR0 84480
#define SM_MBAR1 84488
#define SMEM_TOTAL 84608

__device__ __align__(128) unsigned char g_cb[NCHUNK * CB_CHUNK_BYTES]; // 256KB bf16 swizzled
__device__ float g_c2[K_CL];

__device__ __forceinline__ uint32_t sw128(uint32_t off) { return off ^ ((off >> 3) & 0x70); }

__device__ __forceinline__ uint32_t smem_u32(const void* p) {
    uint32_t a;
    asm("{ .reg .u64 t; cvta.to.shared.u64 t, %1; cvt.u32.u64 %0, t; }" : "=r"(a) : "l"(p));
    return a;
}
__device__ __forceinline__ unsigned long long gptr(const void* p) {
    unsigned long long a;
    asm("cvta.to.global.u64 %0, %1;" : "=l"(a) : "l"(p));
    return a;
}
__device__ __forceinline__ float frcp(float x) {
    float r; asm("rcp.approx.f32 %0, %1;" : "=f"(r) : "f"(x)); return r;
}
__device__ __forceinline__ void ldsm_x4(uint32_t (&r)[4], uint32_t addr) {
    asm volatile("ldmatrix.sync.aligned.m8n8.x4.shared.b16 {%0,%1,%2,%3}, [%4];"
                 : "=r"(r[0]), "=r"(r[1]), "=r"(r[2]), "=r"(r[3]) : "r"(addr));
}
__device__ __forceinline__ void mma16816(float (&d)[4], const uint32_t (&a)[4],
                                         uint32_t b0, uint32_t b1) {
    asm volatile("mma.sync.aligned.m16n8k16.row.col.f32.bf16.bf16.f32 "
                 "{%0,%1,%2,%3}, {%4,%5,%6,%7}, {%8,%9}, {%0,%1,%2,%3};"
                 : "+f"(d[0]), "+f"(d[1]), "+f"(d[2]), "+f"(d[3])
                 : "r"(a[0]), "r"(a[1]), "r"(a[2]), "r"(a[3]), "r"(b0), "r"(b1));
}

#define MBAR_INIT(a, c) \
    asm volatile("mbarrier.init.shared.b64 [%0], %1;" :: "r"(a), "r"(c) : "memory")
#define MBAR_EXPECT_TX(a, n) \
    asm volatile("mbarrier.arrive.expect_tx.shared.b64 _, [%0], %1;" :: "r"(a), "r"(n) : "memory")
#define BULK_G2S(dst, src, n, mbar) \
    asm volatile("cp.async.bulk.shared::cluster.global.mbarrier::complete_tx::bytes " \
                 "[%0], [%1], %2, [%3];" \
                 :: "r"(dst), "l"(src), "r"(n), "r"(mbar) : "memory")
#define MBAR_WAIT(a, ph) do {                                                        \
    uint32_t _m = (a), _p = (ph), _d;                                                \
    asm volatile("{ .reg .pred p; mbarrier.try_wait.parity.acquire.cta.shared::cta.b64 p, [%1], %2;" \
                 " selp.b32 %0, 1, 0, p; }" : "=r"(_d) : "r"(_m), "r"(_p) : "memory"); \
    if (!_d) {                                                                       \
        asm volatile("{ .reg .pred P1; WL_%=:"                                       \
                     " mbarrier.try_wait.parity.acquire.cta.shared::cta.b64 P1, [%0], %1, 0x989680;" \
                     " @P1 bra.uni WD_%=; bra.uni WL_%=; WD_%=: }"                   \
                     :: "r"(_m), "r"(_p) : "memory");                                \
    }                                                                                \
} while (0)

// ---- prepass: clusters fp32 -> bf16 chunk-blocked + SW128-swizzled, plus c2 norms ----
__global__ void prep_c_kernel(const float* __restrict__ C) {
    int w = (blockIdx.x * blockDim.x + threadIdx.x) >> 5;  // one warp per cluster row
    int lane = threadIdx.x & 31;
    if (w >= K_CL) return;
    const float4* src = reinterpret_cast<const float4*>(C + (size_t)w * D_DIM);
    float s = 0.f;
#pragma unroll
    for (int i = 0; i < 4; i++) {
        int f4 = lane + 32 * i;
        float4 v = src[f4];
        s += v.x * v.x + v.y * v.y + v.z * v.z + v.w * v.w;
        __nv_bfloat162 h0 = __float22bfloat162_rn(make_float2(v.x, v.y));
        __nv_bfloat162 h1 = __float22bfloat162_rn(make_float2(v.z, v.w));
        int col = f4 * 4;
        int chunk = col >> 6, kin = col & 63;
        uint32_t off = (uint32_t)chunk * CB_CHUNK_BYTES + sw128((uint32_t)w * 128 + kin * 2);
        *reinterpret_cast<uint2*>(g_cb + off) =
            make_uint2(*(uint32_t*)&h0, *(uint32_t*)&h1);
    }
#pragma unroll
    for (int o = 16; o; o >>= 1) s += __shfl_xor_sync(0xffffffffu, s, o);
    if (lane == 0) g_c2[w] = s;
}

// ---- main fused kernel: BM=64, 8 warps, 32x64 warp tile, bulk-copy B fill ----
extern __shared__ char smem[];

__global__ __launch_bounds__(256, 2)
void cluster_q_kernel(const float* __restrict__ X, float* __restrict__ out) {
    const int tid = threadIdx.x;
    const int lane = tid & 31;
    const int w = tid >> 5, wm = w >> 2, wn = w & 3;
    const int rowBase = blockIdx.x * BM;
    const uint32_t sb = smem_u32(smem);
    const unsigned long long gcb = gptr(g_cb);

    if (tid == 0) {
        MBAR_INIT(sb + SM_MBAR0, 1);
        MBAR_INIT(sb + SM_MBAR1, 1);
    }
    ((float*)(smem + OFF_C2S))[tid] = g_c2[tid];

    // A-load mapping: thread -> row ar, float4 base af; 4 float4/chunk
    const int ar = tid >> 2;
    const int af = tid & 3;
    const float4* Xg = reinterpret_cast<const float4*>(X + (size_t)(rowBase + ar) * D_DIM) + af;

    // hoisted swizzled fragment base offsets; per-ks address = q ^ kb
    uint32_t qA[2], qB[4];
    {
        const uint32_t t16a = (lane >> 4) * 16;
        const uint32_t t16b = ((lane >> 3) & 1) * 16;
#pragma unroll
        for (int mi = 0; mi < 2; mi++) {
            uint32_t row = wm * 32 + mi * 16 + ((lane >> 3) & 1) * 8 + (lane & 7);
            uint32_t base = row * 128;
            qA[mi] = base + (t16a ^ ((base >> 3) & 0x70));
        }
#pragma unroll
        for (int nt = 0; nt < 4; nt++) {
            uint32_t row = wn * 64 + nt * 16 + ((lane >> 4) & 1) * 8 + (lane & 7);
            uint32_t base = row * 128;
            qB[nt] = base + (t16b ^ ((base >> 3) & 0x70));
        }
    }

    float acc[2][8][4];
#pragma unroll
    for (int a = 0; a < 2; a++)
#pragma unroll
        for (int b = 0; b < 8; b++)
#pragma unroll
            for (int c = 0; c < 4; c++) acc[a][b][c] = 0.f;
    float rsx = 0.f;
    float4 xv[4];

    auto loadX = [&](int chunk) {
#pragma unroll
        for (int i = 0; i < 4; i++) xv[i] = Xg[chunk * 16 + 4 * i];
    };
    auto storeA = [&](uint32_t bufoff) {
#pragma unroll
        for (int i = 0; i < 4; i++) {
            float4 v = xv[i];
            rsx = fmaf(v.x, v.x, fmaf(v.y, v.y, fmaf(v.z, v.z, fmaf(v.w, v.w, rsx))));
            __nv_bfloat162 h0 = __float22bfloat162_rn(make_float2(v.x, v.y));
            __nv_bfloat162 h1 = __float22bfloat162_rn(make_float2(v.z, v.w));
            uint32_t off = sw128((uint32_t)ar * 128 + (af + 4 * i) * 8);
            *reinterpret_cast<uint2*>(smem + bufoff + off) =
                make_uint2(*(uint32_t*)&h0, *(uint32_t*)&h1);
        }
    };
    auto mmaChunk = [&](uint32_t aoff, uint32_t boff) {
#pragma unroll
        for (int ks = 0; ks < 4; ks++) {
            const uint32_t kb = ks * 32;
            uint32_t afr[2][4];
#pragma unroll
            for (int mi = 0; mi < 2; mi++) ldsm_x4(afr[mi], sb + aoff + (qA[mi] ^ kb));
#pragma unroll
            for (int nt = 0; nt < 4; nt++) {
                uint32_t bfr[4];
                ldsm_x4(bfr, sb + boff + (qB[nt] ^ kb));
#pragma unroll
                for (int mi = 0; mi < 2; mi++) {
                    mma16816(acc[mi][2 * nt], afr[mi], bfr[0], bfr[1]);
                    mma16816(acc[mi][2 * nt + 1], afr[mi], bfr[2], bfr[3]);
                }
            }
        }
    };

    // prologue: mbar init visible, then bulk-fill B0, convert A0
    __syncthreads();
    if (tid == 0) {
        MBAR_EXPECT_TX(sb + SM_MBAR0, CB_CHUNK_BYTES);
        BULK_G2S(sb + OFF_B0, gcb, CB_CHUNK_BYTES, sb + SM_MBAR0);
    }
    loadX(0);
    storeA(OFF_A0);
    __syncthreads();   // A0 visible

    for (int chunk = 0; chunk < NCHUNK; chunk++) {
        const uint32_t ao = (chunk & 1) ? OFF_A1 : OFF_A0;
        const uint32_t bo = (chunk & 1) ? OFF_B1 : OFF_B0;
        const uint32_t ano = (chunk & 1) ? OFF_A0 : OFF_A1;
        const uint32_t bno = (chunk & 1) ? OFF_B0 : OFF_B1;
        const uint32_t mcur = sb + ((chunk & 1) ? SM_MBAR1 : SM_MBAR0);
        const uint32_t mnext = sb + ((chunk & 1) ? SM_MBAR0 : SM_MBAR1);

        // B-cur ready (bulk writes -> acquire wait orders them for ldsm)
        MBAR_WAIT(mcur, (chunk >> 1) & 1);

        if (chunk + 1 < NCHUNK) {
            // buffer bno & its mbar last touched in chunk-1, all warps past that
            // iteration's __syncthreads -> safe to re-arm and refill
            if (tid == 0) {
                MBAR_EXPECT_TX(mnext, CB_CHUNK_BYTES);
                BULK_G2S(sb + bno, gcb + (unsigned long long)(chunk + 1) * CB_CHUNK_BYTES,
                         CB_CHUNK_BYTES, mnext);
            }
            loadX(chunk + 1);
        }
        mmaChunk(ao, bo);
        if (chunk + 1 < NCHUNK) storeA(ano);
        __syncthreads();
    }

    // x2 norms: 4 lanes share row ar
    rsx += __shfl_xor_sync(0xffffffffu, rsx, 1);
    rsx += __shfl_xor_sync(0xffffffffu, rsx, 2);
    float* x2s = (float*)(smem + OFF_X2S);
    if ((tid & 3) == 0) x2s[ar] = rsx;
    __syncthreads();

    // ---- epilogue phase 1: q (overwrites acc) + row partial sums ----
    float* c2s = (float*)(smem + OFF_C2S);
    float* part = (float*)(smem + OFF_PART);   // [64][4]
    float* invs = (float*)(smem + OFF_INV);

#pragma unroll
    for (int mi = 0; mi < 2; mi++) {
        const int r0 = wm * 32 + mi * 16 + (lane >> 2);
        const float xr0 = x2s[r0];
        const float xr1 = x2s[r0 + 8];
        float p0 = 0.f, p1 = 0.f;
#pragma unroll
        for (int ni = 0; ni < 8; ni++) {
            const int col = wn * 64 + ni * 8 + 2 * (lane & 3);
            const float c20 = c2s[col], c21 = c2s[col + 1];
            float q00 = frcp(1.f + fmaxf(fmaf(-2.f, acc[mi][ni][0], xr0 + c20), 0.f));
            float q01 = frcp(1.f + fmaxf(fmaf(-2.f, acc[mi][ni][1], xr0 + c21), 0.f));
            float q10 = frcp(1.f + fmaxf(fmaf(-2.f, acc[mi][ni][2], xr1 + c20), 0.f));
            float q11 = frcp(1.f + fmaxf(fmaf(-2.f, acc[mi][ni][3], xr1 + c21), 0.f));
            p0 += q00 + q01;
            p1 += q10 + q11;
            acc[mi][ni][0] = q00; acc[mi][ni][1] = q01;
            acc[mi][ni][2] = q10; acc[mi][ni][3] = q11;
        }
        p0 += __shfl_xor_sync(0xffffffffu, p0, 1);
        p0 += __shfl_xor_sync(0xffffffffu, p0, 2);
        p1 += __shfl_xor_sync(0xffffffffu, p1, 1);
        p1 += __shfl_xor_sync(0xffffffffu, p1, 2);
        if ((lane & 3) == 0) {
            part[r0 * 4 + wn] = p0;
            part[(r0 + 8) * 4 + wn] = p1;
        }
    }
    __syncthreads();
    if (tid < 64)
        invs[tid] = frcp(part[tid * 4] + part[tid * 4 + 1] + part[tid * 4 + 2] + part[tid * 4 + 3]);
    __syncthreads();

    // ---- epilogue phase 2: direct fragment stores (no smem staging) ----
#pragma unroll
    for (int mi = 0; mi < 2; mi++) {
        const int r0 = wm * 32 + mi * 16 + (lane >> 2);
        const float iv0 = invs[r0];
        const float iv1 = invs[r0 + 8];
        float* orow0 = out + (size_t)(rowBase + r0) * K_CL;
        float* orow1 = out + (size_t)(rowBase + r0 + 8) * K_CL;
#pragma unroll
        for (int ni = 0; ni < 8; ni++) {
            const int col = wn * 64 + ni * 8 + 2 * (lane & 3);
            *reinterpret_cast<float2*>(&orow0[col]) =
                make_float2(acc[mi][ni][0] * iv0, acc[mi][ni][1] * iv0);
            *reinterpret_cast<float2*>(&orow1[col]) =
                make_float2(acc[mi][ni][2] * iv1, acc[mi][ni][3] * iv1);
        }
    }
}

extern "C" void kernel_launch(void* const* d_in, const int* in_sizes, int n_in,
                              void* d_out, int out_size) {
    const float* X = (const float*)d_in[0];   // [65536, 512]
    const float* C = (const float*)d_in[1];   // [256, 512]
    float* out = (float*)d_out;               // [65536, 256]
    const int n = in_sizes[0] / D_DIM;

    cudaFuncSetAttribute(cluster_q_kernel, cudaFuncAttributeMaxDynamicSharedMemorySize,
                         SMEM_TOTAL);
    prep_c_kernel<<<32, 256>>>(C);
    cluster_q_kernel<<<n / BM, 256, SMEM_TOTAL>>>(X, out);
}